// round 3
// baseline (speedup 1.0000x reference)
#include <cuda_runtime.h>

// HarmonicAwaredAttention — fully fused: one block per sequence n = b*T + t.
// F=128 tokens, C=128 channels, H=2 heads, DH=64, L=4 layers.
// Harmonic mask => sparse attention over offsets {0,±48,±76,±96,±111,±124}.
// R2: 512 threads (4 warps/SMSP), 4x8 per-thread tile, 32-row weight slabs.

#define FDIM 128
#define CDIM 128
#define TT   512
#define NL   4
#define LDA  132          // padded smem row stride (floats)
#define NTHREADS 512

__device__ __forceinline__ unsigned long long pack2(float a) {
    unsigned long long r;
    asm("mov.b64 %0, {%1, %1};" : "=l"(r) : "r"(__float_as_uint(a)));
    return r;
}
__device__ __forceinline__ void ffma2(unsigned long long& d, unsigned long long a,
                                      unsigned long long b) {
    asm("fma.rn.f32x2 %0, %1, %2, %0;" : "+l"(d) : "l"(a), "l"(b));
}

// C[128,128] = A[128,128](smem) @ W[128,128](gmem,L2) + bias.  In-place (Co==A) safe:
// all A reads complete before the final sync; writes happen after it.
// 512 threads: thread (ty=tid>>4 -> 4 rows, tx=tid&15 -> 8 cols).
__device__ void gemm128(const float* __restrict__ A, const float* __restrict__ gW,
                        const float* __restrict__ gB, float* __restrict__ Co,
                        float* __restrict__ wtile, int tid)
{
    const int tx = tid & 15, ty = tid >> 4;
    const int r0 = ty * 4, c0 = tx * 8;

    unsigned long long acc[4][4];
#pragma unroll
    for (int i = 0; i < 4; i++)
#pragma unroll
        for (int p = 0; p < 4; p++) acc[i][p] = 0ull;

    // slab staging: 32 rows x 128 cols, 512 threads load 8 floats each
    const int wrow = tid >> 4;         // 0..31
    const int wcol = (tid & 15) * 8;   // 0..120

    float4 w0 = *(const float4*)&gW[wrow * 128 + wcol];
    float4 w1 = *(const float4*)&gW[wrow * 128 + wcol + 4];

    for (int k0 = 0; k0 < 128; k0 += 32) {
        __syncthreads();                       // previous slab fully consumed
        *(float4*)&wtile[wrow * 128 + wcol]     = w0;
        *(float4*)&wtile[wrow * 128 + wcol + 4] = w1;
        if (k0 + 32 < 128) {                   // prefetch next slab (hidden by compute)
            w0 = *(const float4*)&gW[(k0 + 32 + wrow) * 128 + wcol];
            w1 = *(const float4*)&gW[(k0 + 32 + wrow) * 128 + wcol + 4];
        }
        __syncthreads();                       // slab visible

#pragma unroll
        for (int kk = 0; kk < 32; kk += 4) {
            float4 a4[4];
#pragma unroll
            for (int i = 0; i < 4; i++)
                a4[i] = *(const float4*)&A[(r0 + i) * LDA + k0 + kk];
#pragma unroll
            for (int s = 0; s < 4; s++) {
                const float* wr = &wtile[(kk + s) * 128];
                ulonglong2 bA = *(const ulonglong2*)&wr[c0];
                ulonglong2 bB = *(const ulonglong2*)&wr[c0 + 4];
#pragma unroll
                for (int i = 0; i < 4; i++) {
                    float av = ((const float*)&a4[i])[s];
                    unsigned long long a2 = pack2(av);
                    ffma2(acc[i][0], a2, bA.x);
                    ffma2(acc[i][1], a2, bA.y);
                    ffma2(acc[i][2], a2, bB.x);
                    ffma2(acc[i][3], a2, bB.y);
                }
            }
        }
    }
    __syncthreads();   // all A reads done before any Co writes (enables in-place)

    const float b0 = gB[c0],     b1 = gB[c0 + 1], b2 = gB[c0 + 2], b3 = gB[c0 + 3];
    const float b4 = gB[c0 + 4], b5 = gB[c0 + 5], b6 = gB[c0 + 6], b7 = gB[c0 + 7];
#pragma unroll
    for (int i = 0; i < 4; i++) {
        float* crow = &Co[(r0 + i) * LDA];
        float4 v;
        v.x = __uint_as_float((unsigned)acc[i][0])         + b0;
        v.y = __uint_as_float((unsigned)(acc[i][0] >> 32)) + b1;
        v.z = __uint_as_float((unsigned)acc[i][1])         + b2;
        v.w = __uint_as_float((unsigned)(acc[i][1] >> 32)) + b3;
        *(float4*)&crow[c0] = v;
        v.x = __uint_as_float((unsigned)acc[i][2])         + b4;
        v.y = __uint_as_float((unsigned)(acc[i][2] >> 32)) + b5;
        v.z = __uint_as_float((unsigned)acc[i][3])         + b6;
        v.w = __uint_as_float((unsigned)(acc[i][3] >> 32)) + b7;
        *(float4*)&crow[c0 + 4] = v;
    }
    __syncthreads();   // writeback visible to all
}

// Sparse harmonic attention. Thread (row = tid>>1, head = tid&1) owns one query row.
// Only threads 0..255 participate. Reads q from pQ, K/V from smem; overwrites its
// OWN pQ region with o (disjoint regions per thread -> no internal sync needed).
__device__ void attention(float* __restrict__ pQ, const float* __restrict__ pK,
                          const float* __restrict__ pV, int tid)
{
    const int row  = tid >> 1;
    const int hoff = (tid & 1) * 64;
    const int deltas[11] = {-124, -111, -96, -76, -48, 0, 48, 76, 96, 111, 124};

    float4 q4[16];
    const float* qp = &pQ[row * LDA + hoff];
#pragma unroll
    for (int i = 0; i < 16; i++) q4[i] = *(const float4*)&qp[i * 4];

    float sv[11];
#pragma unroll
    for (int d = 0; d < 11; d++) {
        int j = row + deltas[d];
        float s = -1e30f;
        if ((unsigned)j < 128u) {
            const float* kp = &pK[j * LDA + hoff];
            float a = 0.f;
#pragma unroll
            for (int i = 0; i < 16; i++) {
                float4 kv = *(const float4*)&kp[i * 4];
                a = fmaf(q4[i].x, kv.x, a);
                a = fmaf(q4[i].y, kv.y, a);
                a = fmaf(q4[i].z, kv.z, a);
                a = fmaf(q4[i].w, kv.w, a);
            }
            s = a * 0.125f;    // 1/sqrt(64)
        }
        sv[d] = s;
    }
    float m = sv[0];
#pragma unroll
    for (int d = 1; d < 11; d++) m = fmaxf(m, sv[d]);
    float ev[11];
    float sum = 0.f;
#pragma unroll
    for (int d = 0; d < 11; d++) { float e = expf(sv[d] - m); ev[d] = e; sum += e; }
    const float inv = 1.f / sum;

    float4 o4[16];
#pragma unroll
    for (int i = 0; i < 16; i++) o4[i] = make_float4(0.f, 0.f, 0.f, 0.f);
#pragma unroll
    for (int d = 0; d < 11; d++) {
        int j = row + deltas[d];
        if ((unsigned)j < 128u) {
            float w = ev[d] * inv;
            const float* vp = &pV[j * LDA + hoff];
#pragma unroll
            for (int i = 0; i < 16; i++) {
                float4 vv = *(const float4*)&vp[i * 4];
                o4[i].x = fmaf(w, vv.x, o4[i].x);
                o4[i].y = fmaf(w, vv.y, o4[i].y);
                o4[i].z = fmaf(w, vv.z, o4[i].z);
                o4[i].w = fmaf(w, vv.w, o4[i].w);
            }
        }
    }
    float* op = &pQ[row * LDA + hoff];
#pragma unroll
    for (int i = 0; i < 16; i++) *(float4*)&op[i * 4] = o4[i];
}

extern __shared__ float smem[];

__global__ void __launch_bounds__(NTHREADS, 1)
hattn_kernel(const float* __restrict__ x,
             const float* __restrict__ Wq, const float* __restrict__ bq,
             const float* __restrict__ Wk, const float* __restrict__ bk,
             const float* __restrict__ Wv, const float* __restrict__ bv,
             const float* __restrict__ Wo, const float* __restrict__ bo,
             float* __restrict__ out)
{
    float* bufA  = smem;
    float* bufB  = bufA + 128 * LDA;
    float* bufC  = bufB + 128 * LDA;
    float* wtile = bufC + 128 * LDA;   // [32][128]

    const int tid = threadIdx.x;
    const int b   = blockIdx.x / TT;
    const int t   = blockIdx.x % TT;
    const float* xb = x + (size_t)b * CDIM * TT * FDIM + (size_t)t * FDIM;

    float* pH = bufA;
    float* pK = bufB;
    float* pV = bufC;

    // h[f][c] = x[b][c][t][f] + pe[f][c]
    for (int idx = tid; idx < CDIM * FDIM; idx += NTHREADS) {
        int c = idx >> 7, f = idx & 127;
        float e     = (float)(c & ~1) * (1.0f / 128.0f);
        float denom = exp2f(e * 13.287712379549449f);   // 10000^(i/128)
        float ang   = (float)f / denom;
        float pe    = (c & 1) ? cosf(ang) : sinf(ang);
        pH[f * LDA + c] = xb[(size_t)c * TT * FDIM + f] + pe;
    }
    // gemm's loop-top sync orders the smem fill before first reads

    for (int l = 0; l < NL; l++) {
        const float* wq = Wq + l * 16384; const float* bqv = bq + l * 128;
        const float* wk = Wk + l * 16384; const float* bkv = bk + l * 128;
        const float* wv = Wv + l * 16384; const float* bvv = bv + l * 128;
        const float* wo = Wo + l * 16384; const float* bov = bo + l * 128;

        gemm128(pH, wk, bkv, pK, wtile, tid);   // K
        gemm128(pH, wv, bvv, pV, wtile, tid);   // V
        gemm128(pH, wq, bqv, pH, wtile, tid);   // Q (in-place over H)
        if (tid < 256) attention(pH, pK, pV, tid);  // O overwrites Q (disjoint rows)
        __syncthreads();
        gemm128(pH, wo, bov, pV, wtile, tid);   // H_new = O @ Wo  -> pV
        float* tmp = pH; pH = pV; pV = tmp;
    }

    // out[b][c][t][f] = h[f][c]
    float* ob = out + (size_t)b * CDIM * TT * FDIM + (size_t)t * FDIM;
    for (int idx = tid; idx < CDIM * FDIM; idx += NTHREADS) {
        int c = idx >> 7, f = idx & 127;
        ob[(size_t)c * TT * FDIM + f] = pH[f * LDA + c];
    }
}

extern "C" void kernel_launch(void* const* d_in, const int* in_sizes, int n_in,
                              void* d_out, int out_size)
{
    const float* x  = (const float*)d_in[0];
    const float* Wq = (const float*)d_in[1];
    const float* bq = (const float*)d_in[2];
    const float* Wk = (const float*)d_in[3];
    const float* bk = (const float*)d_in[4];
    const float* Wv = (const float*)d_in[5];
    const float* bv = (const float*)d_in[6];
    const float* Wo = (const float*)d_in[7];
    const float* bo = (const float*)d_in[8];
    float* out = (float*)d_out;

    const int NB = in_sizes[0] / (CDIM * TT * FDIM);   // batch (4)
    const size_t smem_bytes = (size_t)(3 * 128 * LDA + 32 * 128) * sizeof(float); // 219136

    cudaFuncSetAttribute(hattn_kernel, cudaFuncAttributeMaxDynamicSharedMemorySize,
                         (int)smem_bytes);
    hattn_kernel<<<NB * TT, NTHREADS, smem_bytes>>>(x, Wq, bq, Wk, bk, Wv, bv, Wo, bo, out);
}

// round 4
// speedup vs baseline: 1.0011x; 1.0011x over previous
#include <cuda_runtime.h>

// HarmonicAwaredAttention — fully fused: one block per sequence n = b*T + t.
// F=128 tokens, C=128 channels, H=2 heads, DH=64, L=4 layers.
// Harmonic mask => sparse attention over offsets {0,±48,±76,±96,±111,±124}.
// R2: 512 threads (4 warps/SMSP), 4x8 per-thread tile, 32-row weight slabs.

#define FDIM 128
#define CDIM 128
#define TT   512
#define NL   4
#define LDA  132          // padded smem row stride (floats)
#define NTHREADS 512

__device__ __forceinline__ unsigned long long pack2(float a) {
    unsigned long long r;
    asm("mov.b64 %0, {%1, %1};" : "=l"(r) : "r"(__float_as_uint(a)));
    return r;
}
__device__ __forceinline__ void ffma2(unsigned long long& d, unsigned long long a,
                                      unsigned long long b) {
    asm("fma.rn.f32x2 %0, %1, %2, %0;" : "+l"(d) : "l"(a), "l"(b));
}

// C[128,128] = A[128,128](smem) @ W[128,128](gmem,L2) + bias.  In-place (Co==A) safe:
// all A reads complete before the final sync; writes happen after it.
// 512 threads: thread (ty=tid>>4 -> 4 rows, tx=tid&15 -> 8 cols).
__device__ void gemm128(const float* __restrict__ A, const float* __restrict__ gW,
                        const float* __restrict__ gB, float* __restrict__ Co,
                        float* __restrict__ wtile, int tid)
{
    const int tx = tid & 15, ty = tid >> 4;
    const int r0 = ty * 4, c0 = tx * 8;

    unsigned long long acc[4][4];
#pragma unroll
    for (int i = 0; i < 4; i++)
#pragma unroll
        for (int p = 0; p < 4; p++) acc[i][p] = 0ull;

    // slab staging: 32 rows x 128 cols, 512 threads load 8 floats each
    const int wrow = tid >> 4;         // 0..31
    const int wcol = (tid & 15) * 8;   // 0..120

    float4 w0 = *(const float4*)&gW[wrow * 128 + wcol];
    float4 w1 = *(const float4*)&gW[wrow * 128 + wcol + 4];

    for (int k0 = 0; k0 < 128; k0 += 32) {
        __syncthreads();                       // previous slab fully consumed
        *(float4*)&wtile[wrow * 128 + wcol]     = w0;
        *(float4*)&wtile[wrow * 128 + wcol + 4] = w1;
        if (k0 + 32 < 128) {                   // prefetch next slab (hidden by compute)
            w0 = *(const float4*)&gW[(k0 + 32 + wrow) * 128 + wcol];
            w1 = *(const float4*)&gW[(k0 + 32 + wrow) * 128 + wcol + 4];
        }
        __syncthreads();                       // slab visible

#pragma unroll
        for (int kk = 0; kk < 32; kk += 4) {
            float4 a4[4];
#pragma unroll
            for (int i = 0; i < 4; i++)
                a4[i] = *(const float4*)&A[(r0 + i) * LDA + k0 + kk];
#pragma unroll
            for (int s = 0; s < 4; s++) {
                const float* wr = &wtile[(kk + s) * 128];
                ulonglong2 bA = *(const ulonglong2*)&wr[c0];
                ulonglong2 bB = *(const ulonglong2*)&wr[c0 + 4];
#pragma unroll
                for (int i = 0; i < 4; i++) {
                    float av = ((const float*)&a4[i])[s];
                    unsigned long long a2 = pack2(av);
                    ffma2(acc[i][0], a2, bA.x);
                    ffma2(acc[i][1], a2, bA.y);
                    ffma2(acc[i][2], a2, bB.x);
                    ffma2(acc[i][3], a2, bB.y);
                }
            }
        }
    }
    __syncthreads();   // all A reads done before any Co writes (enables in-place)

    const float b0 = gB[c0],     b1 = gB[c0 + 1], b2 = gB[c0 + 2], b3 = gB[c0 + 3];
    const float b4 = gB[c0 + 4], b5 = gB[c0 + 5], b6 = gB[c0 + 6], b7 = gB[c0 + 7];
#pragma unroll
    for (int i = 0; i < 4; i++) {
        float* crow = &Co[(r0 + i) * LDA];
        float4 v;
        v.x = __uint_as_float((unsigned)acc[i][0])         + b0;
        v.y = __uint_as_float((unsigned)(acc[i][0] >> 32)) + b1;
        v.z = __uint_as_float((unsigned)acc[i][1])         + b2;
        v.w = __uint_as_float((unsigned)(acc[i][1] >> 32)) + b3;
        *(float4*)&crow[c0] = v;
        v.x = __uint_as_float((unsigned)acc[i][2])         + b4;
        v.y = __uint_as_float((unsigned)(acc[i][2] >> 32)) + b5;
        v.z = __uint_as_float((unsigned)acc[i][3])         + b6;
        v.w = __uint_as_float((unsigned)(acc[i][3] >> 32)) + b7;
        *(float4*)&crow[c0 + 4] = v;
    }
    __syncthreads();   // writeback visible to all
}

// Sparse harmonic attention. Thread (row = tid>>1, head = tid&1) owns one query row.
// Only threads 0..255 participate. Reads q from pQ, K/V from smem; overwrites its
// OWN pQ region with o (disjoint regions per thread -> no internal sync needed).
__device__ void attention(float* __restrict__ pQ, const float* __restrict__ pK,
                          const float* __restrict__ pV, int tid)
{
    const int row  = tid >> 1;
    const int hoff = (tid & 1) * 64;
    const int deltas[11] = {-124, -111, -96, -76, -48, 0, 48, 76, 96, 111, 124};

    float4 q4[16];
    const float* qp = &pQ[row * LDA + hoff];
#pragma unroll
    for (int i = 0; i < 16; i++) q4[i] = *(const float4*)&qp[i * 4];

    float sv[11];
#pragma unroll
    for (int d = 0; d < 11; d++) {
        int j = row + deltas[d];
        float s = -1e30f;
        if ((unsigned)j < 128u) {
            const float* kp = &pK[j * LDA + hoff];
            float a = 0.f;
#pragma unroll
            for (int i = 0; i < 16; i++) {
                float4 kv = *(const float4*)&kp[i * 4];
                a = fmaf(q4[i].x, kv.x, a);
                a = fmaf(q4[i].y, kv.y, a);
                a = fmaf(q4[i].z, kv.z, a);
                a = fmaf(q4[i].w, kv.w, a);
            }
            s = a * 0.125f;    // 1/sqrt(64)
        }
        sv[d] = s;
    }
    float m = sv[0];
#pragma unroll
    for (int d = 1; d < 11; d++) m = fmaxf(m, sv[d]);
    float ev[11];
    float sum = 0.f;
#pragma unroll
    for (int d = 0; d < 11; d++) { float e = expf(sv[d] - m); ev[d] = e; sum += e; }
    const float inv = 1.f / sum;

    float4 o4[16];
#pragma unroll
    for (int i = 0; i < 16; i++) o4[i] = make_float4(0.f, 0.f, 0.f, 0.f);
#pragma unroll
    for (int d = 0; d < 11; d++) {
        int j = row + deltas[d];
        if ((unsigned)j < 128u) {
            float w = ev[d] * inv;
            const float* vp = &pV[j * LDA + hoff];
#pragma unroll
            for (int i = 0; i < 16; i++) {
                float4 vv = *(const float4*)&vp[i * 4];
                o4[i].x = fmaf(w, vv.x, o4[i].x);
                o4[i].y = fmaf(w, vv.y, o4[i].y);
                o4[i].z = fmaf(w, vv.z, o4[i].z);
                o4[i].w = fmaf(w, vv.w, o4[i].w);
            }
        }
    }
    float* op = &pQ[row * LDA + hoff];
#pragma unroll
    for (int i = 0; i < 16; i++) *(float4*)&op[i * 4] = o4[i];
}

extern __shared__ float smem[];

__global__ void __launch_bounds__(NTHREADS, 1)
hattn_kernel(const float* __restrict__ x,
             const float* __restrict__ Wq, const float* __restrict__ bq,
             const float* __restrict__ Wk, const float* __restrict__ bk,
             const float* __restrict__ Wv, const float* __restrict__ bv,
             const float* __restrict__ Wo, const float* __restrict__ bo,
             float* __restrict__ out)
{
    float* bufA  = smem;
    float* bufB  = bufA + 128 * LDA;
    float* bufC  = bufB + 128 * LDA;
    float* wtile = bufC + 128 * LDA;   // [32][128]

    const int tid = threadIdx.x;
    const int b   = blockIdx.x / TT;
    const int t   = blockIdx.x % TT;
    const float* xb = x + (size_t)b * CDIM * TT * FDIM + (size_t)t * FDIM;

    float* pH = bufA;
    float* pK = bufB;
    float* pV = bufC;

    // h[f][c] = x[b][c][t][f] + pe[f][c]
    for (int idx = tid; idx < CDIM * FDIM; idx += NTHREADS) {
        int c = idx >> 7, f = idx & 127;
        float e     = (float)(c & ~1) * (1.0f / 128.0f);
        float denom = exp2f(e * 13.287712379549449f);   // 10000^(i/128)
        float ang   = (float)f / denom;
        float pe    = (c & 1) ? cosf(ang) : sinf(ang);
        pH[f * LDA + c] = xb[(size_t)c * TT * FDIM + f] + pe;
    }
    // gemm's loop-top sync orders the smem fill before first reads

    for (int l = 0; l < NL; l++) {
        const float* wq = Wq + l * 16384; const float* bqv = bq + l * 128;
        const float* wk = Wk + l * 16384; const float* bkv = bk + l * 128;
        const float* wv = Wv + l * 16384; const float* bvv = bv + l * 128;
        const float* wo = Wo + l * 16384; const float* bov = bo + l * 128;

        gemm128(pH, wk, bkv, pK, wtile, tid);   // K
        gemm128(pH, wv, bvv, pV, wtile, tid);   // V
        gemm128(pH, wq, bqv, pH, wtile, tid);   // Q (in-place over H)
        if (tid < 256) attention(pH, pK, pV, tid);  // O overwrites Q (disjoint rows)
        __syncthreads();
        gemm128(pH, wo, bov, pV, wtile, tid);   // H_new = O @ Wo  -> pV
        float* tmp = pH; pH = pV; pV = tmp;
    }

    // out[b][c][t][f] = h[f][c]
    float* ob = out + (size_t)b * CDIM * TT * FDIM + (size_t)t * FDIM;
    for (int idx = tid; idx < CDIM * FDIM; idx += NTHREADS) {
        int c = idx >> 7, f = idx & 127;
        ob[(size_t)c * TT * FDIM + f] = pH[f * LDA + c];
    }
}

extern "C" void kernel_launch(void* const* d_in, const int* in_sizes, int n_in,
                              void* d_out, int out_size)
{
    const float* x  = (const float*)d_in[0];
    const float* Wq = (const float*)d_in[1];
    const float* bq = (const float*)d_in[2];
    const float* Wk = (const float*)d_in[3];
    const float* bk = (const float*)d_in[4];
    const float* Wv = (const float*)d_in[5];
    const float* bv = (const float*)d_in[6];
    const float* Wo = (const float*)d_in[7];
    const float* bo = (const float*)d_in[8];
    float* out = (float*)d_out;

    const int NB = in_sizes[0] / (CDIM * TT * FDIM);   // batch (4)
    const size_t smem_bytes = (size_t)(3 * 128 * LDA + 32 * 128) * sizeof(float); // 219136

    cudaFuncSetAttribute(hattn_kernel, cudaFuncAttributeMaxDynamicSharedMemorySize,
                         (int)smem_bytes);
    hattn_kernel<<<NB * TT, NTHREADS, smem_bytes>>>(x, Wq, bq, Wk, bk, Wv, bv, Wo, bo, out);
}

// round 6
// speedup vs baseline: 3.9147x; 3.9102x over previous
#include <cuda_runtime.h>
#include <cuda_bf16.h>
#include <cstdint>

// HarmonicAwaredAttention via warp-level HMMA (mma.sync, arch-agnostic PTX).
// One block per sequence n = b*512 + t; 256 threads (8 warps).
// GEMMs: m16n8k16 bf16 MMA, fp32 emulated with bf16 hi/lo 3-term split.
// A: smem bf16 hi/lo [128x136] (ldmatrix). B: gmem fragment-linear (LDG.64, L2).
// Attention: scalar fp32 sparse-harmonic, K/V/Q fp32 in smem.

#define TT 512
#define NTHREADS 256
#define LDH_B  272            // bf16 row stride in bytes (136 elems)
#define LDF    132            // fp32 row stride in floats

// smem byte offsets
#define HHI_OFF 0
#define HLO_OFF 34816
#define QS_OFF  0              // fp32 Q overlays H region (sequenced by syncs)
#define KS_OFF  69632
#define VS_OFF  137216
#define SMEM_TOTAL 204800

// weights, fragment-linear: [gemm][sel hi/lo][ks 0..7][ntile 0..15][lane 0..31] uint2
__device__ __align__(16) uint2 g_wfrag[16 * 8192];
__device__ float g_pe[128 * 128];     // g_pe[c*128 + f]

__device__ __forceinline__ uint32_t smem_u32(const void* p) {
    uint32_t a;
    asm("{ .reg .u64 t; cvta.to.shared.u64 t, %1; cvt.u32.u64 %0, t; }" : "=r"(a) : "l"(p));
    return a;
}

#define LDSM(r, addr) \
    asm volatile("ldmatrix.sync.aligned.m8n8.x4.shared.b16 {%0,%1,%2,%3}, [%4];" \
        : "=r"((r)[0]), "=r"((r)[1]), "=r"((r)[2]), "=r"((r)[3]) : "r"(addr))

#define MMA(dp, a, b) \
    asm volatile("mma.sync.aligned.m16n8k16.row.col.f32.bf16.bf16.f32 " \
        "{%0,%1,%2,%3},{%4,%5,%6,%7},{%8,%9},{%0,%1,%2,%3};" \
        : "+f"((dp)[0]), "+f"((dp)[1]), "+f"((dp)[2]), "+f"((dp)[3]) \
        : "r"((a)[0]), "r"((a)[1]), "r"((a)[2]), "r"((a)[3]), "r"((b).x), "r"((b).y))

// ---------------- prologue: fragment-pack weights + PE table ----------------
// gemm g = 4*layer + {0:Wk,1:Wv,2:Wq,3:Wo}.  B[n][k] = W[k][n].
// entry e: lane=e&31, j=(e>>5)&15 (n-tile), ks=(e>>9)&7, sel=e>>12 (0 hi, 1 lo).
// lane fragment: n = 8j + (lane>>2); k0 = 16ks + 2(lane&3);
// word0 = pack(B[k0][n], B[k0+1][n]); word1 = pack(B[k0+8][n], B[k0+9][n]).
__global__ void prep_w(const float* __restrict__ Wq, const float* __restrict__ Wk,
                       const float* __restrict__ Wv, const float* __restrict__ Wo)
{
    int g = blockIdx.x;
    if (g == 16) {   // PE table
        for (int idx = threadIdx.x; idx < 128 * 128; idx += blockDim.x) {
            int c = idx >> 7, f = idx & 127;
            float e     = (float)(c & ~1) * (1.0f / 128.0f);
            float denom = exp2f(e * 13.287712379549449f);   // 10000^(i/128)
            float ang   = (float)f / denom;
            g_pe[c * 128 + f] = (c & 1) ? cosf(ang) : sinf(ang);
        }
        return;
    }
    int l = g >> 2, m = g & 3;
    const float* src = (m == 0 ? Wk : m == 1 ? Wv : m == 2 ? Wq : Wo) + l * 16384;
    for (int e = threadIdx.x; e < 8192; e += blockDim.x) {
        int lane = e & 31, j = (e >> 5) & 15, ks = (e >> 9) & 7, sel = (e >> 12) & 1;
        int n  = 8 * j + (lane >> 2);
        int k0 = 16 * ks + 2 * (lane & 3);
        float w00 = src[k0 * 128 + n],       w01 = src[(k0 + 1) * 128 + n];
        float w10 = src[(k0 + 8) * 128 + n], w11 = src[(k0 + 9) * 128 + n];
        __nv_bfloat162 p0, p1;
        if (sel == 0) {
            p0 = __floats2bfloat162_rn(w00, w01);
            p1 = __floats2bfloat162_rn(w10, w11);
        } else {
            float h00 = __bfloat162float(__float2bfloat16(w00));
            float h01 = __bfloat162float(__float2bfloat16(w01));
            float h10 = __bfloat162float(__float2bfloat16(w10));
            float h11 = __bfloat162float(__float2bfloat16(w11));
            p0 = __floats2bfloat162_rn(w00 - h00, w01 - h01);
            p1 = __floats2bfloat162_rn(w10 - h10, w11 - h11);
        }
        uint2 o;
        o.x = *(uint32_t*)&p0;
        o.y = *(uint32_t*)&p1;
        g_wfrag[g * 8192 + e] = o;
    }
}

// ---------------- GEMM: D[128x16(warp)] = H(hi+lo) @ B(hi+lo)^T ----------------
__device__ __forceinline__ void gemm_mma(uint32_t a_hi_lane, uint32_t a_lo_lane,
                                         const uint2* __restrict__ wf,
                                         int w, int lane, float (*d)[4])
{
#pragma unroll
    for (int i = 0; i < 16; i++) { d[i][0] = 0.f; d[i][1] = 0.f; d[i][2] = 0.f; d[i][3] = 0.f; }

    const uint2* wf0 = wf + (2 * w) * 32 + lane;   // hi, nt=0; +32 nt=1; +4096 lo
    uint2 bh0 = __ldg(wf0), bh1 = __ldg(wf0 + 32);
    uint2 bl0 = __ldg(wf0 + 4096), bl1 = __ldg(wf0 + 4096 + 32);

#pragma unroll
    for (int ks = 0; ks < 8; ks++) {
        uint2 nh0 = bh0, nh1 = bh1, nl0 = bl0, nl1 = bl1;
        if (ks < 7) {
            const uint2* p = wf0 + (ks + 1) * 512;
            nh0 = __ldg(p); nh1 = __ldg(p + 32);
            nl0 = __ldg(p + 4096); nl1 = __ldg(p + 4096 + 32);
        }
#pragma unroll
        for (int mh = 0; mh < 2; mh++) {
            uint32_t ah[4][4], al[4][4];
#pragma unroll
            for (int m4 = 0; m4 < 4; m4++) {
                uint32_t off = (uint32_t)((mh * 4 + m4) * (16 * LDH_B) + ks * 32);
                LDSM(ah[m4], a_hi_lane + off);
                LDSM(al[m4], a_lo_lane + off);
            }
#pragma unroll
            for (int m4 = 0; m4 < 4; m4++) {
                int mt = mh * 4 + m4;
                MMA(d[mt * 2 + 0], ah[m4], bh0);  MMA(d[mt * 2 + 1], ah[m4], bh1);
                MMA(d[mt * 2 + 0], ah[m4], bl0);  MMA(d[mt * 2 + 1], ah[m4], bl1);
                MMA(d[mt * 2 + 0], al[m4], bh0);  MMA(d[mt * 2 + 1], al[m4], bh1);
            }
        }
        bh0 = nh0; bh1 = nh1; bl0 = nl0; bl1 = nl1;
    }
}

// D + bias -> fp32 smem buffer [128][132]
__device__ __forceinline__ void epi_f32(float (*d)[4], float* buf, const float* bias,
                                        int w, int lane)
{
    int rq = lane >> 2, cq = 2 * (lane & 3);
#pragma unroll
    for (int nt = 0; nt < 2; nt++) {
        int c = 16 * w + 8 * nt + cq;
        float b0 = __ldg(&bias[c]), b1 = __ldg(&bias[c + 1]);
#pragma unroll
        for (int mt = 0; mt < 8; mt++) {
            int r0 = 16 * mt + rq;
            float2 v0 = make_float2(d[mt*2+nt][0] + b0, d[mt*2+nt][1] + b1);
            float2 v1 = make_float2(d[mt*2+nt][2] + b0, d[mt*2+nt][3] + b1);
            *(float2*)&buf[r0 * LDF + c]       = v0;
            *(float2*)&buf[(r0 + 8) * LDF + c] = v1;
        }
    }
}

// D + bias -> bf16 hi/lo H buffers
__device__ __forceinline__ void epi_bf16(float (*d)[4], unsigned char* sm,
                                         const float* bias, int w, int lane)
{
    int rq = lane >> 2, cq = 2 * (lane & 3);
#pragma unroll
    for (int nt = 0; nt < 2; nt++) {
        int c = 16 * w + 8 * nt + cq;
        float b0 = __ldg(&bias[c]), b1 = __ldg(&bias[c + 1]);
#pragma unroll
        for (int mt = 0; mt < 8; mt++) {
            int r0 = 16 * mt + rq;
#pragma unroll
            for (int hh = 0; hh < 2; hh++) {
                int r = r0 + 8 * hh;
                float v0 = d[mt*2+nt][2*hh]     + b0;
                float v1 = d[mt*2+nt][2*hh + 1] + b1;
                __nv_bfloat162 hi2 = __floats2bfloat162_rn(v0, v1);
                float2 hf = __bfloat1622float2(hi2);
                __nv_bfloat162 lo2 = __floats2bfloat162_rn(v0 - hf.x, v1 - hf.y);
                *(uint32_t*)(sm + HHI_OFF + r * LDH_B + c * 2) = *(uint32_t*)&hi2;
                *(uint32_t*)(sm + HLO_OFF + r * LDH_B + c * 2) = *(uint32_t*)&lo2;
            }
        }
    }
}

// D + bias -> gmem out (transposed: out[c][r] with channel stride 65536)
__device__ __forceinline__ void epi_out(float (*d)[4], float* ob, const float* bias,
                                        int w, int lane)
{
    int rq = lane >> 2, cq = 2 * (lane & 3);
#pragma unroll
    for (int nt = 0; nt < 2; nt++) {
        int c = 16 * w + 8 * nt + cq;
        float b0 = __ldg(&bias[c]), b1 = __ldg(&bias[c + 1]);
#pragma unroll
        for (int mt = 0; mt < 8; mt++) {
            int r0 = 16 * mt + rq;
            ob[(size_t)c * 65536 + r0]           = d[mt*2+nt][0] + b0;
            ob[(size_t)(c + 1) * 65536 + r0]     = d[mt*2+nt][1] + b1;
            ob[(size_t)c * 65536 + r0 + 8]       = d[mt*2+nt][2] + b0;
            ob[(size_t)(c + 1) * 65536 + r0 + 8] = d[mt*2+nt][3] + b1;
        }
    }
}

// 64 fp32 vals (one row, one head-half) -> bf16 hi/lo into H buffers
__device__ __forceinline__ void stage_rowvals(const float* v, unsigned char* sm,
                                              int row, int c0)
{
#pragma unroll
    for (int i = 0; i < 32; i++) {
        float a = v[2 * i], b = v[2 * i + 1];
        __nv_bfloat162 hi2 = __floats2bfloat162_rn(a, b);
        float2 hf = __bfloat1622float2(hi2);
        __nv_bfloat162 lo2 = __floats2bfloat162_rn(a - hf.x, b - hf.y);
        *(uint32_t*)(sm + HHI_OFF + row * LDH_B + (c0 + 2 * i) * 2) = *(uint32_t*)&hi2;
        *(uint32_t*)(sm + HLO_OFF + row * LDH_B + (c0 + 2 * i) * 2) = *(uint32_t*)&lo2;
    }
}

extern __shared__ unsigned char smem[];

__global__ void __launch_bounds__(NTHREADS, 1)
hattn_mma(const float* __restrict__ x,
          const float* __restrict__ bq, const float* __restrict__ bk,
          const float* __restrict__ bv, const float* __restrict__ bo,
          float* __restrict__ out)
{
    const int tid = threadIdx.x;
    const int w = tid >> 5, lane = tid & 31;
    const int bi = blockIdx.x / TT;
    const int t  = blockIdx.x % TT;

    float* Qs = (float*)(smem + QS_OFF);
    float* Ks = (float*)(smem + KS_OFF);
    float* Vs = (float*)(smem + VS_OFF);

    const uint32_t smbase = smem_u32(smem);
    const uint32_t a_hi_lane = smbase + HHI_OFF + (lane & 15) * LDH_B + (lane >> 4) * 16;
    const uint32_t a_lo_lane = smbase + HLO_OFF + (lane & 15) * LDH_B + (lane >> 4) * 16;

    // attention / staging thread mapping
    const int row = tid >> 1;
    const int c0  = (tid & 1) * 64;

    // ---- stage H = x + PE ----
    {
        const float* xb = x + (size_t)bi * 8388608 + (size_t)t * 128;
        float v[64];
#pragma unroll
        for (int c = 0; c < 64; c++)
            v[c] = xb[(size_t)(c0 + c) * 65536 + row] + g_pe[(c0 + c) * 128 + row];
        stage_rowvals(v, smem, row, c0);
    }

    const int deltas[11] = {-124, -111, -96, -76, -48, 0, 48, 76, 96, 111, 124};
    float d[16][4];

#pragma unroll 1
    for (int l = 0; l < 4; l++) {
        __syncthreads();                                     // H staged/visible

        gemm_mma(a_hi_lane, a_lo_lane, g_wfrag + (4*l + 0) * 8192, w, lane, d);
        epi_f32(d, Ks, bk + l * 128, w, lane);
        gemm_mma(a_hi_lane, a_lo_lane, g_wfrag + (4*l + 1) * 8192, w, lane, d);
        epi_f32(d, Vs, bv + l * 128, w, lane);
        gemm_mma(a_hi_lane, a_lo_lane, g_wfrag + (4*l + 2) * 8192, w, lane, d);
        __syncthreads();                                     // all H reads done
        epi_f32(d, Qs, bq + l * 128, w, lane);               // Q overlays H region
        __syncthreads();                                     // Q/K/V visible

        // ---- sparse harmonic attention: thread owns (row, head=c0/64) ----
        float o[64];
        {
            float q[64];
            const float* qp = &Qs[row * LDF + c0];
#pragma unroll
            for (int i = 0; i < 64; i++) q[i] = qp[i];

            float sv[11];
#pragma unroll
            for (int dd = 0; dd < 11; dd++) {
                int j = row + deltas[dd];
                float s = -1e30f;
                if ((unsigned)j < 128u) {
                    const float* kp = &Ks[j * LDF + c0];
                    float a = 0.f;
#pragma unroll
                    for (int i = 0; i < 16; i++) {
                        float4 kk = *(const float4*)&kp[i * 4];
                        a = fmaf(q[4*i],   kk.x, a);
                        a = fmaf(q[4*i+1], kk.y, a);
                        a = fmaf(q[4*i+2], kk.z, a);
                        a = fmaf(q[4*i+3], kk.w, a);
                    }
                    s = a * 0.125f;
                }
                sv[dd] = s;
            }
            float m = sv[0];
#pragma unroll
            for (int dd = 1; dd < 11; dd++) m = fmaxf(m, sv[dd]);
            float ev[11], sum = 0.f;
#pragma unroll
            for (int dd = 0; dd < 11; dd++) { float e = expf(sv[dd] - m); ev[dd] = e; sum += e; }
            float inv = 1.f / sum;
#pragma unroll
            for (int i = 0; i < 64; i++) o[i] = 0.f;
#pragma unroll
            for (int dd = 0; dd < 11; dd++) {
                int j = row + deltas[dd];
                if ((unsigned)j < 128u) {
                    float wj = ev[dd] * inv;
                    const float* vp = &Vs[j * LDF + c0];
#pragma unroll
                    for (int i = 0; i < 16; i++) {
                        float4 vv = *(const float4*)&vp[i * 4];
                        o[4*i]   = fmaf(wj, vv.x, o[4*i]);
                        o[4*i+1] = fmaf(wj, vv.y, o[4*i+1]);
                        o[4*i+2] = fmaf(wj, vv.z, o[4*i+2]);
                        o[4*i+3] = fmaf(wj, vv.w, o[4*i+3]);
                    }
                }
            }
        }
        __syncthreads();                                     // all Q reads done
        stage_rowvals(o, smem, row, c0);                     // O -> H buffers
        __syncthreads();                                     // O staged

        gemm_mma(a_hi_lane, a_lo_lane, g_wfrag + (4*l + 3) * 8192, w, lane, d);
        __syncthreads();                                     // all O reads done
        if (l < 3) {
            epi_bf16(d, smem, bo + l * 128, w, lane);        // H_new staged
        } else {
            float* ob = out + (size_t)bi * 8388608 + (size_t)t * 128;
            epi_out(d, ob, bo + l * 128, w, lane);
        }
    }
}

extern "C" void kernel_launch(void* const* d_in, const int* in_sizes, int n_in,
                              void* d_out, int out_size)
{
    const float* x  = (const float*)d_in[0];
    const float* Wq = (const float*)d_in[1];
    const float* bq = (const float*)d_in[2];
    const float* Wk = (const float*)d_in[3];
    const float* bk = (const float*)d_in[4];
    const float* Wv = (const float*)d_in[5];
    const float* bv = (const float*)d_in[6];
    const float* Wo = (const float*)d_in[7];
    const float* bo = (const float*)d_in[8];
    float* out = (float*)d_out;

    const int NB = in_sizes[0] / (128 * TT * 128);   // batch (4)

    prep_w<<<17, 256>>>(Wq, Wk, Wv, Wo);

    cudaFuncSetAttribute(hattn_mma, cudaFuncAttributeMaxDynamicSharedMemorySize, SMEM_TOTAL);
    hattn_mma<<<NB * TT, NTHREADS, SMEM_TOTAL>>>(x, bq, bk, bv, bo, out);
}